// round 15
// baseline (speedup 1.0000x reference)
#include <cuda_runtime.h>

#define N_PTS   65536
#define M_CENT  2048
#define KNN     32
#define IN_DIM  40
#define H1D     64
#define H2D     128
#define OUTD    128
#define NROWS   (M_CENT*KNN)   // 65536

// ---------------- scratch (device globals; no allocation allowed) ----------------
__device__ float  g_h1[NROWS*H1D];      // 16 MB
__device__ float  g_h2[NROWS*H2D];      // 32 MB
__device__ float2 g_rel[NROWS];         // 512 KB
__device__ float2 g_cent[M_CENT];
__device__ float  g_s1[H1D], g_ss1[H1D], g_s2[H2D], g_ss2[H2D];
__device__ unsigned g_prog;             // centroids produced (zero-init at load; monotonic per run)

// ---------------- helpers ----------------
__device__ __forceinline__ unsigned smem_u32(const void* p) {
    return (unsigned)__cvta_generic_to_shared(p);
}
__device__ __forceinline__ unsigned mapa_rank(unsigned laddr, unsigned r) {
    unsigned a;
    asm("mapa.shared::cluster.u32 %0, %1, %2;" : "=r"(a) : "r"(laddr), "r"(r));
    return a;
}
__device__ __forceinline__ unsigned long long f32x2_add(unsigned long long a, unsigned long long b) {
    unsigned long long r;
    asm("add.rn.f32x2 %0, %1, %2;" : "=l"(r) : "l"(a), "l"(b));
    return r;
}
__device__ __forceinline__ unsigned long long f32x2_mul(unsigned long long a, unsigned long long b) {
    unsigned long long r;
    asm("mul.rn.f32x2 %0, %1, %2;" : "=l"(r) : "l"(a), "l"(b));
    return r;
}
__device__ __forceinline__ unsigned long long pk2(float l, float h) {
    unsigned long long r;
    asm("mov.b64 %0, {%1, %2};" : "=l"(r) : "f"(l), "f"(h));
    return r;
}
__device__ __forceinline__ float lo_f(unsigned long long v) { return __uint_as_float((unsigned)v); }
__device__ __forceinline__ float hi_f(unsigned long long v) { return __uint_as_float((unsigned)(v >> 32)); }

// wait on local mbarrier phase with cluster-scope acquire (pairs with st.async tx)
__device__ __forceinline__ void mbar_wait_acq(unsigned addr, unsigned par) {
    asm volatile(
        "{\n\t"
        ".reg .pred P;\n\t"
        "WL_%=:\n\t"
        "mbarrier.try_wait.parity.acquire.cluster.shared::cta.b64 P, [%0], %1, 0x989680;\n\t"
        "@!P bra WL_%=;\n\t"
        "}" :: "r"(addr), "r"(par) : "memory");
}
__device__ __forceinline__ unsigned ld_acq_gpu(const unsigned* p) {
    unsigned v;
    asm volatile("ld.acquire.gpu.global.b32 %0, [%1];" : "=r"(v) : "l"(p) : "memory");
    return v;
}
__device__ __forceinline__ void st_rel_gpu(unsigned* p, unsigned v) {
    asm volatile("st.release.gpu.global.b32 [%0], %1;" :: "l"(p), "r"(v) : "memory");
}

// ---------------- FPS (cluster 0) + ballquery consumers (blocks 16..271), one kernel ----------------
#define FPS_C 16
#define FPS_T 256
#define FPS_PPT 16                       // points per thread
#define FPS_PP2 (FPS_PPT/2)              // packed pairs
#define FPS_W  (FPS_T/32)                // 8 warps
#define FPS_TXB (FPS_C * 16)             // 256 bytes expected per phase
#define BQ_CTAS 256                      // 256 CTAs x 8 warps = 2048 ballquery warps

__global__ void __launch_bounds__(FPS_T,1)
k_fps(const float2* __restrict__ pts, float* __restrict__ cent_dout, int write_dout)
{
    __shared__ unsigned           s_wk[FPS_W];            // per-warp best sv bits
    __shared__ unsigned long long s_wxy[FPS_W];           // per-warp best coords
    __shared__ alignas(16) uint4  s_in[2][FPS_C];         // inbox per source CTA, per parity
    __shared__ alignas(8) unsigned long long s_mbar[2];   // per-parity mbarrier

    int tid  = threadIdx.x;
    int lane = tid & 31;
    int wid  = tid >> 5;

    if (blockIdx.x >= FPS_C) {
        // ================= ballquery consumer path =================
        int gw = ((int)blockIdx.x - FPS_C) * FPS_W + wid;   // one warp per centroid

        // wait until centroid gw is produced (progress > gw)
        while (ld_acq_gpu(&g_prog) <= (unsigned)gw) __nanosleep(200);

        float2 c;
        {   // read via L2 (bypass potentially-stale L1)
            const float2* cp = &g_cent[gw];
            c = __ldcg(cp);
        }
        float c2 = __fadd_rn(__fmul_rn(c.x,c.x), __fmul_rn(c.y,c.y));

        int   cnt  = 0;
        bool  have = false;
        float fx = 0.f, fy = 0.f;

        for (int b = 0; b < N_PTS; b += 32) {
            float2 p   = pts[b + lane];
            float  p2  = __fadd_rn(__fmul_rn(p.x,p.x), __fmul_rn(p.y,p.y));
            float  dot = __fadd_rn(__fmul_rn(c.x,p.x), __fmul_rn(c.y,p.y));
            float  dd  = __fsub_rn(__fadd_rn(c2, p2), __fmul_rn(2.0f, dot));
            bool hit = (dd <= 0.0025f);
            unsigned m = __ballot_sync(0xFFFFFFFFu, hit);
            float rx = __fsub_rn(p.x, c.x), ry = __fsub_rn(p.y, c.y);
            if (!have && m) {
                int src = __ffs(m) - 1;
                fx = __shfl_sync(0xFFFFFFFFu, rx, src);
                fy = __shfl_sync(0xFFFFFFFFu, ry, src);
                have = true;
            }
            int pos = cnt + __popc(m & ((1u << lane) - 1u));
            if (hit && pos < KNN) g_rel[gw*KNN + pos] = make_float2(rx, ry);
            cnt += __popc(m);
            if (cnt >= KNN) break;
        }
        for (int s2 = cnt + lane; s2 < KNN; s2 += 32)
            g_rel[gw*KNN + s2] = make_float2(fx, fy);
        return;
    }

    // ================= FPS producer path (cluster 0) =================
    unsigned rank; asm("mov.u32 %0, %%cluster_ctarank;" : "=r"(rank));
    int gtid = (int)rank * FPS_T + tid;
    int base = gtid * FPS_PPT;

    unsigned mb0 = smem_u32(&s_mbar[0]);
    unsigned mb1 = smem_u32(&s_mbar[1]);

    if (tid == 0) {
        asm volatile("mbarrier.init.shared.b64 [%0], %1;" :: "r"(mb0), "r"(1u) : "memory");
        asm volatile("mbarrier.init.shared.b64 [%0], %1;" :: "r"(mb1), "r"(1u) : "memory");
        asm volatile("mbarrier.arrive.expect_tx.shared.b64 _, [%0], %1;" :: "r"(mb0), "r"((unsigned)FPS_TXB) : "memory");
        asm volatile("mbarrier.arrive.expect_tx.shared.b64 _, [%0], %1;" :: "r"(mb1), "r"((unsigned)FPS_TXB) : "memory");
    }

    // folded k_init: rank 1 zeroes the BN accumulators (graph replays!)
    if (rank == 1) {
        if (tid < H1D) { g_s1[tid] = 0.f; g_ss1[tid] = 0.f; }
        if (tid < H2D) { g_s2[tid] = 0.f; g_ss2[tid] = 0.f; }
    }

    // hoisted st.async destination addresses (lane L -> CTA L), both parities
    unsigned rd0 = 0, rd1 = 0, rb0 = 0, rb1 = 0;
    if (wid == 0 && lane < FPS_C) {
        rd0 = mapa_rank(smem_u32(&s_in[0][rank]), (unsigned)lane);
        rd1 = mapa_rank(smem_u32(&s_in[1][rank]), (unsigned)lane);
        rb0 = mapa_rank(mb0, (unsigned)lane);
        rb1 = mapa_rank(mb1, (unsigned)lane);
    }

    // register-resident points (packed pairs) + min-dist^2
    unsigned long long px2[FPS_PP2], py2[FPS_PP2];
    float d2[FPS_PPT];
    {
        const float4* p4 = (const float4*)pts;
        #pragma unroll
        for (int i = 0; i < FPS_PP2; i++) {
            float4 v = p4[(base >> 1) + i];
            px2[i] = pk2(v.x, v.z);
            py2[i] = pk2(v.y, v.w);
            d2[2*i]   = __int_as_float(0x7f800000);
            d2[2*i+1] = __int_as_float(0x7f800000);
        }
    }

    float2 p0 = pts[0];
    float cx = p0.x, cy = p0.y;
    if (rank == 0 && tid == 0) {
        g_cent[0] = p0;
        if (write_dout) { cent_dout[0] = p0.x; cent_dout[1] = p0.y; }
        st_rel_gpu(&g_prog, 1u);    // publish centroid 0
    }

    // mbarrier init + arming must be cluster-visible before any st.async arrives
    __syncthreads();
    asm volatile("barrier.cluster.arrive.aligned;" ::: "memory");
    asm volatile("barrier.cluster.wait.aligned;"   ::: "memory");

    for (int s = 1; s < M_CENT; s++) {
        int p = s & 1;
        unsigned q = (unsigned)(((s - 1) >> 1) & 1);   // phase parity of mbar[p] for this use
        unsigned long long ncx2 = pk2(-cx, -cx);
        unsigned long long ncy2 = pk2(-cy, -cy);

        // scan: update running min-dist^2, track max of mins.
        // prev center's own dd == 0 exactly -> implicit dist.at[prev].set(0)
        float bm = -1.0f;
        #pragma unroll
        for (int i = 0; i < FPS_PP2; i++) {
            unsigned long long dx2 = f32x2_add(px2[i], ncx2);
            unsigned long long dy2 = f32x2_add(py2[i], ncy2);
            unsigned long long dd2 = f32x2_add(f32x2_mul(dx2, dx2), f32x2_mul(dy2, dy2));
            float nd0 = fminf(d2[2*i],   lo_f(dd2));
            float nd1 = fminf(d2[2*i+1], hi_f(dd2));
            d2[2*i]   = nd0;
            d2[2*i+1] = nd1;
            bm = fmaxf(bm, nd0);
            bm = fmaxf(bm, nd1);
        }
        // reference dist domain: sqrt(d2 + 1e-12); sv >= 0 so bits compare as u32
        unsigned sv = __float_as_uint(sqrtf(__fadd_rn(bm, 1e-12f)));

        // single-instruction warp max (latency hides under the match chain below)
        unsigned wmax = __reduce_max_sync(0xFFFFFFFFu, sv);

        // recover coords of FIRST j matching bm (reverse select chain -> smallest j wins)
        float bx = 0.f, by = 0.f;
        #pragma unroll
        for (int i = FPS_PP2 - 1; i >= 0; i--) {
            if (d2[2*i+1] == bm) { bx = hi_f(px2[i]); by = hi_f(py2[i]); }
            if (d2[2*i]   == bm) { bx = lo_f(px2[i]); by = lo_f(py2[i]); }
        }

        // winner lane = lowest lane hitting wmax (lane order == gtid order == point order)
        unsigned wb  = __ballot_sync(0xFFFFFFFFu, sv == wmax);
        int      src = __ffs(wb) - 1;
        float wx = __shfl_sync(0xFFFFFFFFu, bx, src);
        float wy = __shfl_sync(0xFFFFFFFFu, by, src);
        if (lane == 0) { s_wk[wid] = wmax; s_wxy[wid] = pk2(wx, wy); }
        __syncthreads();

        // warp 0: block reduce over 8 warp slots, then st.async the CTA-best into
        // every CTA's inbox slot [rank] + complete_tx on that CTA's mbarrier.
        if (wid == 0) {
            unsigned k = (lane < FPS_W) ? s_wk[lane] : 0u;
            unsigned bmax = __reduce_max_sync(0xFFFFFFFFu, k);
            unsigned bb   = __ballot_sync(0xFFFFFFFFu, k == bmax);
            int      bsrc = __ffs(bb) - 1;          // lowest warp slot = lowest gtid
            unsigned long long bxy = s_wxy[bsrc];   // LDS broadcast (same addr all lanes)
            if (lane < FPS_C) {
                unsigned rdata = p ? rd1 : rd0;
                unsigned rmbar = p ? rb1 : rb0;
                asm volatile(
                    "st.async.shared::cluster.mbarrier::complete_tx::bytes.v4.b32 "
                    "[%0], {%1, %2, %3, %4}, [%5];"
                    :: "r"(rdata), "r"(bmax), "r"(0u),
                       "r"((unsigned)bxy), "r"((unsigned)(bxy >> 32)), "r"(rmbar) : "memory");
            }
        }

        // all warps: wait for 16 messages (256 tx bytes) on the local mbarrier
        unsigned mba = p ? mb1 : mb0;
        mbar_wait_acq(mba, q);

        // re-arm this parity's mbarrier for its next use (2 iterations later).
        if (tid == 0) {
            asm volatile("mbarrier.arrive.expect_tx.shared.b64 _, [%0], %1;"
                         :: "r"(mba), "r"((unsigned)FPS_TXB) : "memory");
        }

        // every warp reduces the 16 CTA-bests from LOCAL smem (LDS ~29 cyc)
        unsigned rk = 0u, rxlo = 0u, rxhi = 0u;
        if (lane < FPS_C) {
            uint4 m = s_in[p][lane];
            rk = m.x; rxlo = m.z; rxhi = m.w;
        }
        unsigned cmax = __reduce_max_sync(0xFFFFFFFFu, rk);
        unsigned cb   = __ballot_sync(0xFFFFFFFFu, rk == cmax);
        int      csrc = __ffs(cb) - 1;              // lowest rank = lowest gtid
        cx = __uint_as_float(__shfl_sync(0xFFFFFFFFu, rxlo, csrc));
        cy = __uint_as_float(__shfl_sync(0xFFFFFFFFu, rxhi, csrc));

        if (rank == 0 && tid == 0) {
            g_cent[s] = make_float2(cx, cy);
            if (write_dout) { cent_dout[2*s] = cx; cent_dout[2*s+1] = cy; }
            st_rel_gpu(&g_prog, (unsigned)(s + 1));   // publish centroid s
        }
    }

    // no CTA exits while peers' st.async traffic may still target its smem
    asm volatile("barrier.cluster.arrive.aligned;" ::: "memory");
    asm volatile("barrier.cluster.wait.aligned;"   ::: "memory");
}

// ---------------- layer1: freq-encode + [65536x40]@[40x64] + b1 ----------------
__global__ __launch_bounds__(128) void k_layer1(const float* __restrict__ W1,
                                                const float* __restrict__ b1)
{
    __shared__ float ws[IN_DIM*H1D];   // 10 KB
    __shared__ float bs[H1D];
    int tid = threadIdx.x;
    for (int i = tid; i < IN_DIM*H1D; i += 128) ws[i] = W1[i];
    if (tid < H1D) bs[tid] = b1[tid];
    __syncthreads();

    int r = blockIdx.x * 128 + tid;
    float2 q = g_rel[r];

    float acc[H1D];
    #pragma unroll
    for (int j = 0; j < H1D; j++) acc[j] = bs[j];

    for (int f = 0; f < 10; f++) {
        float fr = 3.14159265358979f * (float)(1 << f);
        float e0, e1, e2, e3;
        sincosf(__fmul_rn(q.x, fr), &e0, &e1);
        sincosf(__fmul_rn(q.y, fr), &e2, &e3);
        const float* w0 = &ws[(4*f + 0)*H1D];
        const float* w1 = &ws[(4*f + 1)*H1D];
        const float* w2 = &ws[(4*f + 2)*H1D];
        const float* w3 = &ws[(4*f + 3)*H1D];
        #pragma unroll
        for (int j = 0; j < H1D; j++) {
            acc[j] = fmaf(e0, w0[j], acc[j]);
            acc[j] = fmaf(e1, w1[j], acc[j]);
            acc[j] = fmaf(e2, w2[j], acc[j]);
            acc[j] = fmaf(e3, w3[j], acc[j]);
        }
    }
    float4* o = (float4*)&g_h1[(size_t)r * H1D];
    #pragma unroll
    for (int j = 0; j < H1D/4; j++)
        o[j] = make_float4(acc[4*j], acc[4*j+1], acc[4*j+2], acc[4*j+3]);
}

// ---------------- column sum / sumsq reduction (layer1 output only) ----------------
__global__ __launch_bounds__(256) void k_red1()
{
    __shared__ float sh_s[256], sh_q[256];
    const int C = H1D;
    int tid = threadIdx.x;
    int col = tid & (C - 1);
    int sub = tid / C;
    const int L = 256 / C;
    int row0 = blockIdx.x * (NROWS / 256);
    float s = 0.f, q = 0.f;
    for (int r = sub; r < NROWS/256; r += L) {
        float v = g_h1[(size_t)(row0 + r) * C + col];
        s += v;
        q  = fmaf(v, v, q);
    }
    sh_s[tid] = s; sh_q[tid] = q;
    __syncthreads();
    if (tid < C) {
        float ts = 0.f, tq = 0.f;
        #pragma unroll
        for (int u = 0; u < L; u++) { ts += sh_s[u*C + tid]; tq += sh_q[u*C + tid]; }
        atomicAdd(&g_s1[tid], ts);
        atomicAdd(&g_ss1[tid], tq);
    }
}

// ---------------- layer2: BN1+ReLU then [65536x64]@[64x128] + b2; fused col-stats of h2 ----------------
__global__ __launch_bounds__(128) void k_layer2(const float* __restrict__ W2,
                                                const float* __restrict__ b2,
                                                const float* __restrict__ g1,
                                                const float* __restrict__ be1)
{
    __shared__ float xs[32*H1D];
    __shared__ float sc[H1D], sh[H1D];
    int tid = threadIdx.x;
    if (tid < H1D) {
        float m  = g_s1[tid]  * (1.0f/NROWS);
        float v  = g_ss1[tid] * (1.0f/NROWS) - m*m;
        float rs = rsqrtf(v + 1e-5f);
        float scale = g1[tid] * rs;
        sc[tid] = scale;
        sh[tid] = be1[tid] - m * scale;
    }
    __syncthreads();

    int row0 = blockIdx.x * 32;
    for (int t = tid; t < 32*H1D; t += 128) {
        int c = t & (H1D - 1);
        float v = g_h1[(size_t)row0 * H1D + t];
        xs[t] = fmaxf(fmaf(v, sc[c], sh[c]), 0.0f);
    }
    __syncthreads();

    int j = tid;
    float acc[32];
    float bj = b2[j];
    #pragma unroll
    for (int r = 0; r < 32; r++) acc[r] = bj;
    for (int i = 0; i < H1D; i++) {
        float w = __ldg(&W2[i*H2D + j]);
        #pragma unroll
        for (int r = 0; r < 32; r++)
            acc[r] = fmaf(xs[r*H1D + i], w, acc[r]);
    }
    // write h2 + fused per-block column stats (thread j owns column j's 32 rows)
    float cs = 0.f, cq = 0.f;
    #pragma unroll
    for (int r = 0; r < 32; r++) {
        g_h2[(size_t)(row0 + r) * H2D + j] = acc[r];
        cs += acc[r];
        cq  = fmaf(acc[r], acc[r], cq);
    }
    atomicAdd(&g_s2[j], cs);
    atomicAdd(&g_ss2[j], cq);
}

// ---------------- layer3: BN2+ReLU, [32x128]@[128x128]+b3, max over 32 ----------------
__global__ __launch_bounds__(128) void k_layer3(const float* __restrict__ W3,
                                                const float* __restrict__ b3,
                                                const float* __restrict__ g2,
                                                const float* __restrict__ be2,
                                                float* __restrict__ out)
{
    __shared__ float xs[32*H2D];
    __shared__ float sc[H2D], sh[H2D];
    int tid = threadIdx.x;
    {
        float m  = g_s2[tid]  * (1.0f/NROWS);
        float v  = g_ss2[tid] * (1.0f/NROWS) - m*m;
        float rs = rsqrtf(v + 1e-5f);
        float scale = g2[tid] * rs;
        sc[tid] = scale;
        sh[tid] = be2[tid] - m * scale;
    }
    __syncthreads();

    int row0 = blockIdx.x * 32;
    for (int t = tid; t < 32*H2D; t += 128) {
        int c = t & (H2D - 1);
        float v = g_h2[(size_t)row0 * H2D + t];
        xs[t] = fmaxf(fmaf(v, sc[c], sh[c]), 0.0f);
    }
    __syncthreads();

    int j = tid;
    float acc[32];
    float bj = b3[j];
    #pragma unroll
    for (int r = 0; r < 32; r++) acc[r] = bj;
    for (int i = 0; i < H2D; i++) {
        float w = __ldg(&W3[i*OUTD + j]);
        #pragma unroll
        for (int r = 0; r < 32; r++)
            acc[r] = fmaf(xs[r*H2D + i], w, acc[r]);
    }
    float mv = acc[0];
    #pragma unroll
    for (int r = 1; r < 32; r++) mv = fmaxf(mv, acc[r]);
    out[(size_t)blockIdx.x * OUTD + j] = mv;
}

// ---------------- launch ----------------
extern "C" void kernel_launch(void* const* d_in, const int* in_sizes, int n_in,
                              void* d_out, int out_size)
{
    const float2* pts = (const float2*)d_in[0];
    const float* W1  = (const float*)d_in[1];
    const float* b1  = (const float*)d_in[2];
    const float* g1  = (const float*)d_in[3];
    const float* be1 = (const float*)d_in[4];
    const float* W2  = (const float*)d_in[5];
    const float* b2  = (const float*)d_in[6];
    const float* g2  = (const float*)d_in[7];
    const float* be2 = (const float*)d_in[8];
    const float* W3  = (const float*)d_in[9];
    const float* b3  = (const float*)d_in[10];

    float* out = (float*)d_out;
    float* cent_out = out + (size_t)M_CENT * OUTD;
    int wd = (out_size >= M_CENT*OUTD + M_CENT*2) ? 1 : 0;

    // FPS cluster (blocks 0-15) + ballquery consumers (blocks 16-271), one kernel
    cudaFuncSetAttribute(k_fps, cudaFuncAttributeNonPortableClusterSizeAllowed, 1);
    {
        cudaLaunchConfig_t cfg = {};
        cfg.gridDim  = dim3(FPS_C + BQ_CTAS, 1, 1);   // 272 = 17 clusters of 16
        cfg.blockDim = dim3(FPS_T, 1, 1);
        cfg.dynamicSmemBytes = 0;
        cfg.stream = 0;
        cudaLaunchAttribute attrs[1];
        attrs[0].id = cudaLaunchAttributeClusterDimension;
        attrs[0].val.clusterDim.x = FPS_C;
        attrs[0].val.clusterDim.y = 1;
        attrs[0].val.clusterDim.z = 1;
        cfg.attrs = attrs;
        cfg.numAttrs = 1;
        cudaLaunchKernelEx(&cfg, k_fps, pts, cent_out, wd);
    }

    k_layer1<<<NROWS/128, 128>>>(W1, b1);
    k_red1<<<256, 256>>>();
    k_layer2<<<NROWS/32, 128>>>(W2, b2, g1, be1);
    k_layer3<<<M_CENT, 128>>>(W3, b3, g2, be2, out);
}

// round 16
// speedup vs baseline: 1.3572x; 1.3572x over previous
#include <cuda_runtime.h>

#define N_PTS   65536
#define M_CENT  2048
#define KNN     32
#define IN_DIM  40
#define H1D     64
#define H2D     128
#define OUTD    128
#define NROWS   (M_CENT*KNN)   // 65536

// ---------------- scratch (device globals; no allocation allowed) ----------------
__device__ float  g_h1[NROWS*H1D];      // 16 MB
__device__ float  g_h2[NROWS*H2D];      // 32 MB
__device__ float2 g_rel[NROWS];         // 512 KB
__device__ float2 g_cent[M_CENT];
__device__ float  g_s1[H1D], g_ss1[H1D], g_s2[H2D], g_ss2[H2D];

// ---------------- helpers ----------------
__device__ __forceinline__ unsigned smem_u32(const void* p) {
    return (unsigned)__cvta_generic_to_shared(p);
}
__device__ __forceinline__ unsigned mapa_rank(unsigned laddr, unsigned r) {
    unsigned a;
    asm("mapa.shared::cluster.u32 %0, %1, %2;" : "=r"(a) : "r"(laddr), "r"(r));
    return a;
}
__device__ __forceinline__ unsigned long long f32x2_add(unsigned long long a, unsigned long long b) {
    unsigned long long r;
    asm("add.rn.f32x2 %0, %1, %2;" : "=l"(r) : "l"(a), "l"(b));
    return r;
}
__device__ __forceinline__ unsigned long long f32x2_mul(unsigned long long a, unsigned long long b) {
    unsigned long long r;
    asm("mul.rn.f32x2 %0, %1, %2;" : "=l"(r) : "l"(a), "l"(b));
    return r;
}
__device__ __forceinline__ unsigned long long pk2(float l, float h) {
    unsigned long long r;
    asm("mov.b64 %0, {%1, %2};" : "=l"(r) : "f"(l), "f"(h));
    return r;
}
__device__ __forceinline__ float lo_f(unsigned long long v) { return __uint_as_float((unsigned)v); }
__device__ __forceinline__ float hi_f(unsigned long long v) { return __uint_as_float((unsigned)(v >> 32)); }

// wait on local mbarrier phase with cluster-scope acquire (pairs with st.async tx)
__device__ __forceinline__ void mbar_wait_acq(unsigned addr, unsigned par) {
    asm volatile(
        "{\n\t"
        ".reg .pred P;\n\t"
        "WL_%=:\n\t"
        "mbarrier.try_wait.parity.acquire.cluster.shared::cta.b64 P, [%0], %1, 0x989680;\n\t"
        "@!P bra WL_%=;\n\t"
        "}" :: "r"(addr), "r"(par) : "memory");
}

// ---------------- FPS: 16-CTA cluster; st.async push + mbarrier tx completion ----------------
#define FPS_C 16
#define FPS_T 256
#define FPS_PPT 16                       // points per thread
#define FPS_PP2 (FPS_PPT/2)              // packed pairs
#define FPS_W  (FPS_T/32)                // 8 warps
#define FPS_TXB (FPS_C * 16)             // 256 bytes expected per phase

__global__ void __launch_bounds__(FPS_T,1)
k_fps(const float2* __restrict__ pts, float* __restrict__ cent_dout, int write_dout)
{
    __shared__ unsigned           s_wk[FPS_W];            // per-warp best sv bits
    __shared__ unsigned long long s_wxy[FPS_W];           // per-warp best coords
    __shared__ alignas(16) uint4  s_in[2][FPS_C];         // inbox per source CTA, per parity
    __shared__ alignas(8) unsigned long long s_mbar[2];   // per-parity mbarrier

    unsigned rank; asm("mov.u32 %0, %%cluster_ctarank;" : "=r"(rank));
    int tid  = threadIdx.x;
    int lane = tid & 31;
    int wid  = tid >> 5;
    int gtid = (int)rank * FPS_T + tid;
    int base = gtid * FPS_PPT;

    unsigned mb0 = smem_u32(&s_mbar[0]);
    unsigned mb1 = smem_u32(&s_mbar[1]);

    if (tid == 0) {
        asm volatile("mbarrier.init.shared.b64 [%0], %1;" :: "r"(mb0), "r"(1u) : "memory");
        asm volatile("mbarrier.init.shared.b64 [%0], %1;" :: "r"(mb1), "r"(1u) : "memory");
        asm volatile("mbarrier.arrive.expect_tx.shared.b64 _, [%0], %1;" :: "r"(mb0), "r"((unsigned)FPS_TXB) : "memory");
        asm volatile("mbarrier.arrive.expect_tx.shared.b64 _, [%0], %1;" :: "r"(mb1), "r"((unsigned)FPS_TXB) : "memory");
    }

    // folded k_init: rank 1 zeroes the BN accumulators (graph replays!)
    if (rank == 1) {
        if (tid < H1D) { g_s1[tid] = 0.f; g_ss1[tid] = 0.f; }
        if (tid < H2D) { g_s2[tid] = 0.f; g_ss2[tid] = 0.f; }
    }

    // hoisted st.async destination addresses (lane L -> CTA L), both parities
    unsigned rd0 = 0, rd1 = 0, rb0 = 0, rb1 = 0;
    if (wid == 0 && lane < FPS_C) {
        rd0 = mapa_rank(smem_u32(&s_in[0][rank]), (unsigned)lane);
        rd1 = mapa_rank(smem_u32(&s_in[1][rank]), (unsigned)lane);
        rb0 = mapa_rank(mb0, (unsigned)lane);
        rb1 = mapa_rank(mb1, (unsigned)lane);
    }

    // register-resident points (packed pairs) + min-dist^2
    unsigned long long px2[FPS_PP2], py2[FPS_PP2];
    float d2[FPS_PPT];
    {
        const float4* p4 = (const float4*)pts;
        #pragma unroll
        for (int i = 0; i < FPS_PP2; i++) {
            float4 v = p4[(base >> 1) + i];
            px2[i] = pk2(v.x, v.z);
            py2[i] = pk2(v.y, v.w);
            d2[2*i]   = __int_as_float(0x7f800000);
            d2[2*i+1] = __int_as_float(0x7f800000);
        }
    }

    float2 p0 = pts[0];
    float cx = p0.x, cy = p0.y;
    if (rank == 0 && tid == 0) {
        g_cent[0] = p0;
        if (write_dout) { cent_dout[0] = p0.x; cent_dout[1] = p0.y; }
    }

    // mbarrier init + arming must be cluster-visible before any st.async arrives
    __syncthreads();
    asm volatile("barrier.cluster.arrive.aligned;" ::: "memory");
    asm volatile("barrier.cluster.wait.aligned;"   ::: "memory");

    for (int s = 1; s < M_CENT; s++) {
        int p = s & 1;
        unsigned q = (unsigned)(((s - 1) >> 1) & 1);   // phase parity of mbar[p] for this use
        unsigned long long ncx2 = pk2(-cx, -cx);
        unsigned long long ncy2 = pk2(-cy, -cy);

        // scan: update running min-dist^2, track max of mins.
        // prev center's own dd == 0 exactly -> implicit dist.at[prev].set(0)
        float bm = -1.0f;
        #pragma unroll
        for (int i = 0; i < FPS_PP2; i++) {
            unsigned long long dx2 = f32x2_add(px2[i], ncx2);
            unsigned long long dy2 = f32x2_add(py2[i], ncy2);
            unsigned long long dd2 = f32x2_add(f32x2_mul(dx2, dx2), f32x2_mul(dy2, dy2));
            float nd0 = fminf(d2[2*i],   lo_f(dd2));
            float nd1 = fminf(d2[2*i+1], hi_f(dd2));
            d2[2*i]   = nd0;
            d2[2*i+1] = nd1;
            bm = fmaxf(bm, nd0);
            bm = fmaxf(bm, nd1);
        }
        // reference dist domain: sqrt(d2 + 1e-12); sv >= 0 so bits compare as u32
        unsigned sv = __float_as_uint(sqrtf(__fadd_rn(bm, 1e-12f)));

        // single-instruction warp max (latency hides under the match chain below)
        unsigned wmax = __reduce_max_sync(0xFFFFFFFFu, sv);

        // recover coords of FIRST j matching bm (reverse select chain -> smallest j wins)
        float bx = 0.f, by = 0.f;
        #pragma unroll
        for (int i = FPS_PP2 - 1; i >= 0; i--) {
            if (d2[2*i+1] == bm) { bx = hi_f(px2[i]); by = hi_f(py2[i]); }
            if (d2[2*i]   == bm) { bx = lo_f(px2[i]); by = lo_f(py2[i]); }
        }

        // winner lane = lowest lane hitting wmax (lane order == gtid order == point order)
        unsigned wb  = __ballot_sync(0xFFFFFFFFu, sv == wmax);
        int      src = __ffs(wb) - 1;
        float wx = __shfl_sync(0xFFFFFFFFu, bx, src);
        float wy = __shfl_sync(0xFFFFFFFFu, by, src);
        if (lane == 0) { s_wk[wid] = wmax; s_wxy[wid] = pk2(wx, wy); }
        __syncthreads();

        // warp 0: block reduce over 8 warp slots, then st.async the CTA-best into
        // every CTA's inbox slot [rank] + complete_tx on that CTA's mbarrier.
        if (wid == 0) {
            unsigned k = (lane < FPS_W) ? s_wk[lane] : 0u;
            unsigned bmax = __reduce_max_sync(0xFFFFFFFFu, k);
            unsigned bb   = __ballot_sync(0xFFFFFFFFu, k == bmax);
            int      bsrc = __ffs(bb) - 1;          // lowest warp slot = lowest gtid
            unsigned long long bxy = s_wxy[bsrc];   // LDS broadcast (same addr all lanes)
            if (lane < FPS_C) {
                unsigned rdata = p ? rd1 : rd0;
                unsigned rmbar = p ? rb1 : rb0;
                asm volatile(
                    "st.async.shared::cluster.mbarrier::complete_tx::bytes.v4.b32 "
                    "[%0], {%1, %2, %3, %4}, [%5];"
                    :: "r"(rdata), "r"(bmax), "r"(0u),
                       "r"((unsigned)bxy), "r"((unsigned)(bxy >> 32)), "r"(rmbar) : "memory");
            }
        }

        // all warps: wait for 16 messages (256 tx bytes) on the local mbarrier
        unsigned mba = p ? mb1 : mb0;
        mbar_wait_acq(mba, q);

        // re-arm this parity's mbarrier for its next use (2 iterations later).
        if (tid == 0) {
            asm volatile("mbarrier.arrive.expect_tx.shared.b64 _, [%0], %1;"
                         :: "r"(mba), "r"((unsigned)FPS_TXB) : "memory");
        }

        // every warp reduces the 16 CTA-bests from LOCAL smem (LDS ~29 cyc)
        unsigned rk = 0u, rxlo = 0u, rxhi = 0u;
        if (lane < FPS_C) {
            uint4 m = s_in[p][lane];
            rk = m.x; rxlo = m.z; rxhi = m.w;
        }
        unsigned cmax = __reduce_max_sync(0xFFFFFFFFu, rk);
        unsigned cb   = __ballot_sync(0xFFFFFFFFu, rk == cmax);
        int      csrc = __ffs(cb) - 1;              // lowest rank = lowest gtid
        cx = __uint_as_float(__shfl_sync(0xFFFFFFFFu, rxlo, csrc));
        cy = __uint_as_float(__shfl_sync(0xFFFFFFFFu, rxhi, csrc));

        if (rank == 0 && tid == 0) {
            g_cent[s] = make_float2(cx, cy);
            if (write_dout) { cent_dout[2*s] = cx; cent_dout[2*s+1] = cy; }
        }
    }

    // no CTA exits while peers' st.async traffic may still target its smem
    asm volatile("barrier.cluster.arrive.aligned;" ::: "memory");
    asm volatile("barrier.cluster.wait.aligned;"   ::: "memory");
}

// ---------------- ball query: 1 warp / centroid, first-K by index ----------------
__global__ __launch_bounds__(1024) void k_ballquery(const float2* __restrict__ pts)
{
    int gw   = (blockIdx.x * blockDim.x + threadIdx.x) >> 5;
    int lane = threadIdx.x & 31;
    if (gw >= M_CENT) return;

    float2 c  = g_cent[gw];
    float  c2 = __fadd_rn(__fmul_rn(c.x,c.x), __fmul_rn(c.y,c.y));

    int   cnt  = 0;
    bool  have = false;
    float fx = 0.f, fy = 0.f;

    for (int b = 0; b < N_PTS; b += 32) {
        float2 p   = pts[b + lane];
        float  p2  = __fadd_rn(__fmul_rn(p.x,p.x), __fmul_rn(p.y,p.y));
        float  dot = __fadd_rn(__fmul_rn(c.x,p.x), __fmul_rn(c.y,p.y));
        float  dd  = __fsub_rn(__fadd_rn(c2, p2), __fmul_rn(2.0f, dot));
        bool hit = (dd <= 0.0025f);
        unsigned m = __ballot_sync(0xFFFFFFFFu, hit);
        float rx = __fsub_rn(p.x, c.x), ry = __fsub_rn(p.y, c.y);
        if (!have && m) {
            int src = __ffs(m) - 1;
            fx = __shfl_sync(0xFFFFFFFFu, rx, src);
            fy = __shfl_sync(0xFFFFFFFFu, ry, src);
            have = true;
        }
        int pos = cnt + __popc(m & ((1u << lane) - 1u));
        if (hit && pos < KNN) g_rel[gw*KNN + pos] = make_float2(rx, ry);
        cnt += __popc(m);
        if (cnt >= KNN) break;
    }
    for (int s2 = cnt + lane; s2 < KNN; s2 += 32)
        g_rel[gw*KNN + s2] = make_float2(fx, fy);
}

// ---------------- layer1: freq-encode + [65536x40]@[40x64] + b1 ----------------
__global__ __launch_bounds__(128) void k_layer1(const float* __restrict__ W1,
                                                const float* __restrict__ b1)
{
    __shared__ float ws[IN_DIM*H1D];   // 10 KB
    __shared__ float bs[H1D];
    int tid = threadIdx.x;
    for (int i = tid; i < IN_DIM*H1D; i += 128) ws[i] = W1[i];
    if (tid < H1D) bs[tid] = b1[tid];
    __syncthreads();

    int r = blockIdx.x * 128 + tid;
    float2 q = g_rel[r];

    float acc[H1D];
    #pragma unroll
    for (int j = 0; j < H1D; j++) acc[j] = bs[j];

    for (int f = 0; f < 10; f++) {
        float fr = 3.14159265358979f * (float)(1 << f);
        float e0, e1, e2, e3;
        sincosf(__fmul_rn(q.x, fr), &e0, &e1);
        sincosf(__fmul_rn(q.y, fr), &e2, &e3);
        const float* w0 = &ws[(4*f + 0)*H1D];
        const float* w1 = &ws[(4*f + 1)*H1D];
        const float* w2 = &ws[(4*f + 2)*H1D];
        const float* w3 = &ws[(4*f + 3)*H1D];
        #pragma unroll
        for (int j = 0; j < H1D; j++) {
            acc[j] = fmaf(e0, w0[j], acc[j]);
            acc[j] = fmaf(e1, w1[j], acc[j]);
            acc[j] = fmaf(e2, w2[j], acc[j]);
            acc[j] = fmaf(e3, w3[j], acc[j]);
        }
    }
    float4* o = (float4*)&g_h1[(size_t)r * H1D];
    #pragma unroll
    for (int j = 0; j < H1D/4; j++)
        o[j] = make_float4(acc[4*j], acc[4*j+1], acc[4*j+2], acc[4*j+3]);
}

// ---------------- column sum / sumsq reduction (layer1 output only) ----------------
__global__ __launch_bounds__(256) void k_red1()
{
    __shared__ float sh_s[256], sh_q[256];
    const int C = H1D;
    int tid = threadIdx.x;
    int col = tid & (C - 1);
    int sub = tid / C;
    const int L = 256 / C;
    int row0 = blockIdx.x * (NROWS / 256);
    float s = 0.f, q = 0.f;
    for (int r = sub; r < NROWS/256; r += L) {
        float v = g_h1[(size_t)(row0 + r) * C + col];
        s += v;
        q  = fmaf(v, v, q);
    }
    sh_s[tid] = s; sh_q[tid] = q;
    __syncthreads();
    if (tid < C) {
        float ts = 0.f, tq = 0.f;
        #pragma unroll
        for (int u = 0; u < L; u++) { ts += sh_s[u*C + tid]; tq += sh_q[u*C + tid]; }
        atomicAdd(&g_s1[tid], ts);
        atomicAdd(&g_ss1[tid], tq);
    }
}

// ---------------- layer2: BN1+ReLU then [65536x64]@[64x128] + b2; fused col-stats of h2 ----------------
__global__ __launch_bounds__(128) void k_layer2(const float* __restrict__ W2,
                                                const float* __restrict__ b2,
                                                const float* __restrict__ g1,
                                                const float* __restrict__ be1)
{
    __shared__ alignas(16) float xs[32*H1D];
    __shared__ float sc[H1D], sh[H1D];
    int tid = threadIdx.x;
    if (tid < H1D) {
        float m  = g_s1[tid]  * (1.0f/NROWS);
        float v  = g_ss1[tid] * (1.0f/NROWS) - m*m;
        float rs = rsqrtf(v + 1e-5f);
        float scale = g1[tid] * rs;
        sc[tid] = scale;
        sh[tid] = be1[tid] - m * scale;
    }
    __syncthreads();

    int row0 = blockIdx.x * 32;
    for (int t = tid; t < 32*H1D; t += 128) {
        int c = t & (H1D - 1);
        float v = g_h1[(size_t)row0 * H1D + t];
        xs[t] = fmaxf(fmaf(v, sc[c], sh[c]), 0.0f);
    }
    __syncthreads();

    int j = tid;
    float acc[32];
    float bj = b2[j];
    #pragma unroll
    for (int r = 0; r < 32; r++) acc[r] = bj;
    // vectorized: LDS.128 broadcast of 4 consecutive i per r (i-order preserved)
    for (int i = 0; i < H1D; i += 4) {
        float w0 = __ldg(&W2[(i+0)*H2D + j]);
        float w1 = __ldg(&W2[(i+1)*H2D + j]);
        float w2 = __ldg(&W2[(i+2)*H2D + j]);
        float w3 = __ldg(&W2[(i+3)*H2D + j]);
        #pragma unroll
        for (int r = 0; r < 32; r++) {
            float4 xv = *(const float4*)&xs[r*H1D + i];
            acc[r] = fmaf(xv.x, w0, acc[r]);
            acc[r] = fmaf(xv.y, w1, acc[r]);
            acc[r] = fmaf(xv.z, w2, acc[r]);
            acc[r] = fmaf(xv.w, w3, acc[r]);
        }
    }
    // write h2 + fused per-block column stats (thread j owns column j's 32 rows)
    float cs = 0.f, cq = 0.f;
    #pragma unroll
    for (int r = 0; r < 32; r++) {
        g_h2[(size_t)(row0 + r) * H2D + j] = acc[r];
        cs += acc[r];
        cq  = fmaf(acc[r], acc[r], cq);
    }
    atomicAdd(&g_s2[j], cs);
    atomicAdd(&g_ss2[j], cq);
}

// ---------------- layer3: BN2+ReLU, [32x128]@[128x128]+b3, max over 32 ----------------
__global__ __launch_bounds__(128) void k_layer3(const float* __restrict__ W3,
                                                const float* __restrict__ b3,
                                                const float* __restrict__ g2,
                                                const float* __restrict__ be2,
                                                float* __restrict__ out)
{
    __shared__ alignas(16) float xs[32*H2D];
    __shared__ float sc[H2D], sh[H2D];
    int tid = threadIdx.x;
    {
        float m  = g_s2[tid]  * (1.0f/NROWS);
        float v  = g_ss2[tid] * (1.0f/NROWS) - m*m;
        float rs = rsqrtf(v + 1e-5f);
        float scale = g2[tid] * rs;
        sc[tid] = scale;
        sh[tid] = be2[tid] - m * scale;
    }
    __syncthreads();

    int row0 = blockIdx.x * 32;
    for (int t = tid; t < 32*H2D; t += 128) {
        int c = t & (H2D - 1);
        float v = g_h2[(size_t)row0 * H2D + t];
        xs[t] = fmaxf(fmaf(v, sc[c], sh[c]), 0.0f);
    }
    __syncthreads();

    int j = tid;
    float acc[32];
    float bj = b3[j];
    #pragma unroll
    for (int r = 0; r < 32; r++) acc[r] = bj;
    // vectorized: LDS.128 broadcast of 4 consecutive i per r (i-order preserved)
    for (int i = 0; i < H2D; i += 4) {
        float w0 = __ldg(&W3[(i+0)*OUTD + j]);
        float w1 = __ldg(&W3[(i+1)*OUTD + j]);
        float w2 = __ldg(&W3[(i+2)*OUTD + j]);
        float w3 = __ldg(&W3[(i+3)*OUTD + j]);
        #pragma unroll
        for (int r = 0; r < 32; r++) {
            float4 xv = *(const float4*)&xs[r*H2D + i];
            acc[r] = fmaf(xv.x, w0, acc[r]);
            acc[r] = fmaf(xv.y, w1, acc[r]);
            acc[r] = fmaf(xv.z, w2, acc[r]);
            acc[r] = fmaf(xv.w, w3, acc[r]);
        }
    }
    float mv = acc[0];
    #pragma unroll
    for (int r = 1; r < 32; r++) mv = fmaxf(mv, acc[r]);
    out[(size_t)blockIdx.x * OUTD + j] = mv;
}

// ---------------- launch ----------------
extern "C" void kernel_launch(void* const* d_in, const int* in_sizes, int n_in,
                              void* d_out, int out_size)
{
    const float2* pts = (const float2*)d_in[0];
    const float* W1  = (const float*)d_in[1];
    const float* b1  = (const float*)d_in[2];
    const float* g1  = (const float*)d_in[3];
    const float* be1 = (const float*)d_in[4];
    const float* W2  = (const float*)d_in[5];
    const float* b2  = (const float*)d_in[6];
    const float* g2  = (const float*)d_in[7];
    const float* be2 = (const float*)d_in[8];
    const float* W3  = (const float*)d_in[9];
    const float* b3  = (const float*)d_in[10];

    float* out = (float*)d_out;
    float* cent_out = out + (size_t)M_CENT * OUTD;
    int wd = (out_size >= M_CENT*OUTD + M_CENT*2) ? 1 : 0;

    // FPS: 16-CTA cluster (non-portable size) via cudaLaunchKernelEx
    cudaFuncSetAttribute(k_fps, cudaFuncAttributeNonPortableClusterSizeAllowed, 1);
    {
        cudaLaunchConfig_t cfg = {};
        cfg.gridDim  = dim3(FPS_C, 1, 1);
        cfg.blockDim = dim3(FPS_T, 1, 1);
        cfg.dynamicSmemBytes = 0;
        cfg.stream = 0;
        cudaLaunchAttribute attrs[1];
        attrs[0].id = cudaLaunchAttributeClusterDimension;
        attrs[0].val.clusterDim.x = FPS_C;
        attrs[0].val.clusterDim.y = 1;
        attrs[0].val.clusterDim.z = 1;
        cfg.attrs = attrs;
        cfg.numAttrs = 1;
        cudaLaunchKernelEx(&cfg, k_fps, pts, cent_out, wd);
    }

    k_ballquery<<<64, 1024>>>(pts);
    k_layer1<<<NROWS/128, 128>>>(W1, b1);
    k_red1<<<256, 256>>>();
    k_layer2<<<NROWS/32, 128>>>(W2, b2, g1, be1);
    k_layer3<<<M_CENT, 128>>>(W3, b3, g2, be2, out);
}